// round 12
// baseline (speedup 1.0000x reference)
#include <cuda_runtime.h>
#include <cuda_fp16.h>
#include <cstdint>

#define D    128
#define BM   128
#define NMAX 100000
#define LDH  136   // padded row stride in halves (272B: conflict-free ldmatrix)

// fp16 node features for the edge gather (51MB working set fits L2).
__device__ __half g_hp [(size_t)NMAX * D];
__device__ __half g_hpH[(size_t)NMAX * D];

__device__ __forceinline__ uint32_t h2u(__half2 v) {
    return *reinterpret_cast<uint32_t*>(&v);
}

__device__ __forceinline__ void mma16816(float* c,
                                         uint32_t a0, uint32_t a1,
                                         uint32_t a2, uint32_t a3,
                                         uint32_t b0, uint32_t b1) {
    asm volatile(
        "mma.sync.aligned.m16n8k16.row.col.f32.f16.f16.f32 "
        "{%0,%1,%2,%3}, {%4,%5,%6,%7}, {%8,%9}, {%0,%1,%2,%3};"
        : "+f"(c[0]), "+f"(c[1]), "+f"(c[2]), "+f"(c[3])
        : "r"(a0), "r"(a1), "r"(a2), "r"(a3), "r"(b0), "r"(b1));
}
__device__ __forceinline__ void ldm_x4(uint32_t& r0, uint32_t& r1,
                                       uint32_t& r2, uint32_t& r3,
                                       const __half* p) {
    uint32_t a = (uint32_t)__cvta_generic_to_shared(p);
    asm volatile("ldmatrix.sync.aligned.m8n8.x4.shared.b16 {%0,%1,%2,%3}, [%4];"
                 : "=r"(r0), "=r"(r1), "=r"(r2), "=r"(r3) : "r"(a));
}
__device__ __forceinline__ void ldm_x4_t(uint32_t& r0, uint32_t& r1,
                                         uint32_t& r2, uint32_t& r3,
                                         const __half* p) {
    uint32_t a = (uint32_t)__cvta_generic_to_shared(p);
    asm volatile("ldmatrix.sync.aligned.m8n8.x4.trans.shared.b16 {%0,%1,%2,%3}, [%4];"
                 : "=r"(r0), "=r"(r1), "=r"(r2), "=r"(r3) : "r"(a));
}

// ============================================================================
// Node transform: hp = h@W^T + b ; hpH = hp@H.  fp16 HMMA, fp32 accumulate.
// 8 warps as 4(m) x 2(n): warp tile = 32 rows x 64 cols. All fragment loads
// via ldmatrix.x4. hp/hpH staged in smem, stored coalesced.
// ============================================================================
__global__ __launch_bounds__(256, 1)
void node_kernel(const float* __restrict__ h,
                 const float* __restrict__ Ww,
                 const float* __restrict__ Wb,
                 const float* __restrict__ Hm,
                 int N)
{
    extern __shared__ char smem[];
    float*  bias = reinterpret_cast<float*>(smem);            // 512 B
    __half* As   = reinterpret_cast<__half*>(smem + 512);     // h tile -> hp   [128][LDH]
    __half* Ws   = As + 128 * LDH;                            // W (n-major) -> hpH stage
    __half* Hs   = Ws + 128 * LDH;                            // H (k-major)   [128][LDH]

    const int tid  = threadIdx.x;
    const int row0 = blockIdx.x * BM;

    if (tid < 128) bias[tid] = Wb[tid];

    // ---- stage h, W, H: row r = tid>>1, each thread covers 64 cols ----
    {
        const int r  = tid >> 1;
        const int hf = tid & 1;
        int grow = row0 + r; if (grow >= N) grow = N - 1;
        const float4* hr = reinterpret_cast<const float4*>(h  + (size_t)grow * D);
        const float4* wr = reinterpret_cast<const float4*>(Ww + (size_t)r    * D);
        const float4* mr = reinterpret_cast<const float4*>(Hm + (size_t)r    * D);
        #pragma unroll 4
        for (int u = 0; u < 16; ++u) {
            const int c = hf * 64 + u * 4;
            float4 v = hr[hf * 16 + u];
            uint2 p;
            p.x = h2u(__floats2half2_rn(v.x, v.y));
            p.y = h2u(__floats2half2_rn(v.z, v.w));
            *reinterpret_cast<uint2*>(&As[r * LDH + c]) = p;
            v = wr[hf * 16 + u];
            p.x = h2u(__floats2half2_rn(v.x, v.y));
            p.y = h2u(__floats2half2_rn(v.z, v.w));
            *reinterpret_cast<uint2*>(&Ws[r * LDH + c]) = p;
            v = mr[hf * 16 + u];
            p.x = h2u(__floats2half2_rn(v.x, v.y));
            p.y = h2u(__floats2half2_rn(v.z, v.w));
            *reinterpret_cast<uint2*>(&Hs[r * LDH + c]) = p;
        }
    }
    __syncthreads();

    const int warp = tid >> 5;
    const int lane = tid & 31;
    const int m0   = (warp >> 1) * 32;       // warp row base
    const int n0   = (warp & 1) * 64;        // warp col base
    const int qr   = lane >> 2;
    const int qc   = (lane & 3) * 2;

    // per-lane ldmatrix address components
    const int aRow = (lane & 15);            // + (lane>>4)*8 cols
    const int aCol = (lane >> 4) * 8;
    const int bRow = ((lane >> 4) << 3) + (lane & 7);   // n-major B (Ws)
    const int bCol = ((lane >> 3) & 1) * 8;
    const int tRow = ((lane >> 3) & 1) * 8 + (lane & 7); // trans B (Hs): k-row
    const int tCol = (lane >> 4) * 8;

    float acc[2][8][4];
    #pragma unroll
    for (int mt = 0; mt < 2; ++mt)
        #pragma unroll
        for (int nt = 0; nt < 8; ++nt)
            #pragma unroll
            for (int j = 0; j < 4; ++j) acc[mt][nt][j] = 0.f;

    // ================= GEMM1: hp = h @ W^T =================
    #pragma unroll
    for (int ks = 0; ks < 8; ++ks) {
        const int kb = ks * 16;
        uint32_t A[2][4];
        #pragma unroll
        for (int mt = 0; mt < 2; ++mt)
            ldm_x4(A[mt][0], A[mt][1], A[mt][2], A[mt][3],
                   &As[(m0 + mt * 16 + aRow) * LDH + kb + aCol]);
        #pragma unroll
        for (int np = 0; np < 4; ++np) {
            uint32_t b0, b1, b2, b3;
            ldm_x4(b0, b1, b2, b3,
                   &Ws[(n0 + np * 16 + bRow) * LDH + kb + bCol]);
            #pragma unroll
            for (int mt = 0; mt < 2; ++mt) {
                mma16816(acc[mt][2 * np],     A[mt][0], A[mt][1], A[mt][2], A[mt][3], b0, b1);
                mma16816(acc[mt][2 * np + 1], A[mt][0], A[mt][1], A[mt][2], A[mt][3], b2, b3);
            }
        }
    }

    __syncthreads();   // all GEMM1 reads of As/Ws complete

    // ---- epilogue 1: +bias, f16, scatter into As (hp) ----
    #pragma unroll
    for (int mt = 0; mt < 2; ++mt) {
        const int r = m0 + mt * 16 + qr;
        #pragma unroll
        for (int nt = 0; nt < 8; ++nt) {
            const int c = n0 + nt * 8 + qc;
            const float b0f = bias[c], b1f = bias[c + 1];
            *reinterpret_cast<uint32_t*>(&As[r * LDH + c]) =
                h2u(__floats2half2_rn(acc[mt][nt][0] + b0f, acc[mt][nt][1] + b1f));
            *reinterpret_cast<uint32_t*>(&As[(r + 8) * LDH + c]) =
                h2u(__floats2half2_rn(acc[mt][nt][2] + b0f, acc[mt][nt][3] + b1f));
        }
    }
    __syncthreads();   // hp visible to all

    // ---- coalesced g_hp store from smem ----
    {
        const int r  = tid >> 1;
        const int hf = tid & 1;
        const int grow = row0 + r;
        if (grow < N) {
            const uint4* srcp = reinterpret_cast<const uint4*>(&As[r * LDH + hf * 64]);
            uint4* dstp = reinterpret_cast<uint4*>(&g_hp[(size_t)grow * D + hf * 64]);
            #pragma unroll
            for (int u = 0; u < 8; ++u) dstp[u] = srcp[u];
        }
    }

    // ================= GEMM2: hpH = hp @ H =================
    #pragma unroll
    for (int mt = 0; mt < 2; ++mt)
        #pragma unroll
        for (int nt = 0; nt < 8; ++nt)
            #pragma unroll
            for (int j = 0; j < 4; ++j) acc[mt][nt][j] = 0.f;

    #pragma unroll
    for (int ks = 0; ks < 8; ++ks) {
        const int kb = ks * 16;
        uint32_t A[2][4];
        #pragma unroll
        for (int mt = 0; mt < 2; ++mt)
            ldm_x4(A[mt][0], A[mt][1], A[mt][2], A[mt][3],
                   &As[(m0 + mt * 16 + aRow) * LDH + kb + aCol]);
        #pragma unroll
        for (int np = 0; np < 4; ++np) {
            uint32_t b0, b1, b2, b3;
            ldm_x4_t(b0, b1, b2, b3,
                     &Hs[(kb + tRow) * LDH + n0 + np * 16 + tCol]);
            #pragma unroll
            for (int mt = 0; mt < 2; ++mt) {
                mma16816(acc[mt][2 * np],     A[mt][0], A[mt][1], A[mt][2], A[mt][3], b0, b1);
                mma16816(acc[mt][2 * np + 1], A[mt][0], A[mt][1], A[mt][2], A[mt][3], b2, b3);
            }
        }
    }

    // ---- epilogue 2: f16, scatter into Ws (hpH stage; Ws reads done at s2) ----
    #pragma unroll
    for (int mt = 0; mt < 2; ++mt) {
        const int r = m0 + mt * 16 + qr;
        #pragma unroll
        for (int nt = 0; nt < 8; ++nt) {
            const int c = n0 + nt * 8 + qc;
            *reinterpret_cast<uint32_t*>(&Ws[r * LDH + c]) =
                h2u(__floats2half2_rn(acc[mt][nt][0], acc[mt][nt][1]));
            *reinterpret_cast<uint32_t*>(&Ws[(r + 8) * LDH + c]) =
                h2u(__floats2half2_rn(acc[mt][nt][2], acc[mt][nt][3]));
        }
    }
    __syncthreads();

    // ---- coalesced g_hpH store ----
    {
        const int r  = tid >> 1;
        const int hf = tid & 1;
        const int grow = row0 + r;
        if (grow < N) {
            const uint4* srcp = reinterpret_cast<const uint4*>(&Ws[r * LDH + hf * 64]);
            uint4* dstp = reinterpret_cast<uint4*>(&g_hpH[(size_t)grow * D + hf * 64]);
            #pragma unroll
            for (int u = 0; u < 8; ++u) dstp[u] = srcp[u];
        }
    }
}

// ============================================================================
// Edge kernel: 2 edges per warp, 16 lanes x 16B per fp16 row. (unchanged)
// ============================================================================
__global__ __launch_bounds__(256)
void edge_kernel(const int* __restrict__ src,
                 const int* __restrict__ dst,
                 float* __restrict__ out, int E, int N)
{
    int gw   = (int)((blockIdx.x * blockDim.x + threadIdx.x) >> 5);
    int lane = threadIdx.x & 31;
    int e    = gw * 2 + (lane >> 4);
    if (e >= E) return;
    int slot = lane & 15;

    int s = __ldg(src + e);
    int d = __ldg(dst + e);
    s = min(max(s, 0), N - 1);
    d = min(max(d, 0), N - 1);

    uint4 a = reinterpret_cast<const uint4*>(g_hp  + (size_t)s * D)[slot];
    uint4 b = reinterpret_cast<const uint4*>(g_hpH + (size_t)d * D)[slot];

    const __half2* ah = reinterpret_cast<const __half2*>(&a);
    const __half2* bh = reinterpret_cast<const __half2*>(&b);
    float sum = 0.f;
    #pragma unroll
    for (int i = 0; i < 4; ++i) {
        float2 fa = __half22float2(ah[i]);
        float2 fb = __half22float2(bh[i]);
        float dx = fa.x - fb.x, dy = fa.y - fb.y;
        sum = fmaf(dx, dx, sum);
        sum = fmaf(dy, dy, sum);
    }
    #pragma unroll
    for (int off = 8; off; off >>= 1)
        sum += __shfl_xor_sync(0xffffffffu, sum, off);

    if (slot == 0) out[e] = sum;
}

extern "C" void kernel_launch(void* const* d_in, const int* in_sizes, int n_in,
                              void* d_out, int out_size)
{
    const float* h   = (const float*)d_in[0];
    const int*   src = (const int*)d_in[1];
    const int*   dst = (const int*)d_in[2];
    const float* Ww  = (const float*)d_in[3];
    const float* Wb  = (const float*)d_in[4];
    const float* Hm  = (const float*)d_in[5];
    float*       out = (float*)d_out;

    int N = in_sizes[0] / D;
    if (N > NMAX) N = NMAX;
    int E = in_sizes[1];

    const int smem_bytes = 512 + 3 * 128 * LDH * (int)sizeof(__half); // 104960 B
    cudaFuncSetAttribute(node_kernel,
                         cudaFuncAttributeMaxDynamicSharedMemorySize, smem_bytes);

    int nblocks = (N + BM - 1) / BM;
    node_kernel<<<nblocks, 256, smem_bytes>>>(h, Ww, Wb, Hm, N);

    int eblocks = (E / 2 + 7) / 8;   // 8 warps = 16 edges per block
    edge_kernel<<<eblocks, 256>>>(src, dst, out, E, N);
}

// round 15
// speedup vs baseline: 1.1270x; 1.1270x over previous
#include <cuda_runtime.h>
#include <cuda_fp16.h>
#include <cstdint>

#define D    128
#define BM   128
#define NMAX 100000
#define LDH  136   // padded row stride in halves (272B: conflict-free ldmatrix)

// fp16 node features for the edge gather (51MB working set fits L2).
__device__ __half g_hp [(size_t)NMAX * D];
__device__ __half g_hpH[(size_t)NMAX * D];

__device__ __forceinline__ uint32_t h2u(__half2 v) {
    return *reinterpret_cast<uint32_t*>(&v);
}

__device__ __forceinline__ void mma16816(float* c,
                                         uint32_t a0, uint32_t a1,
                                         uint32_t a2, uint32_t a3,
                                         uint32_t b0, uint32_t b1) {
    asm volatile(
        "mma.sync.aligned.m16n8k16.row.col.f32.f16.f16.f32 "
        "{%0,%1,%2,%3}, {%4,%5,%6,%7}, {%8,%9}, {%0,%1,%2,%3};"
        : "+f"(c[0]), "+f"(c[1]), "+f"(c[2]), "+f"(c[3])
        : "r"(a0), "r"(a1), "r"(a2), "r"(a3), "r"(b0), "r"(b1));
}
__device__ __forceinline__ void ldm_x4(uint32_t& r0, uint32_t& r1,
                                       uint32_t& r2, uint32_t& r3,
                                       const __half* p) {
    uint32_t a = (uint32_t)__cvta_generic_to_shared(p);
    asm volatile("ldmatrix.sync.aligned.m8n8.x4.shared.b16 {%0,%1,%2,%3}, [%4];"
                 : "=r"(r0), "=r"(r1), "=r"(r2), "=r"(r3) : "r"(a));
}
__device__ __forceinline__ void ldm_x4_t(uint32_t& r0, uint32_t& r1,
                                         uint32_t& r2, uint32_t& r3,
                                         const __half* p) {
    uint32_t a = (uint32_t)__cvta_generic_to_shared(p);
    asm volatile("ldmatrix.sync.aligned.m8n8.x4.trans.shared.b16 {%0,%1,%2,%3}, [%4];"
                 : "=r"(r0), "=r"(r1), "=r"(r2), "=r"(r3) : "r"(a));
}

// ============================================================================
// Node transform: hp = h@W^T + b ; hpH = hp@H.  fp16 HMMA, fp32 accumulate.
// 512 threads = 16 warps as 4(m) x 4(n); warp tile = 32 rows x 32 cols.
// 4 warps/SMSP to hide LDG/LDS/HMMA latencies (node was latency-bound at 8).
// ============================================================================
__global__ __launch_bounds__(512, 1)
void node_kernel(const float* __restrict__ h,
                 const float* __restrict__ Ww,
                 const float* __restrict__ Wb,
                 const float* __restrict__ Hm,
                 int N)
{
    extern __shared__ char smem[];
    float*  bias = reinterpret_cast<float*>(smem);            // 512 B
    __half* As   = reinterpret_cast<__half*>(smem + 512);     // h tile -> hp   [128][LDH]
    __half* Ws   = As + 128 * LDH;                            // W (n-major) -> hpH stage
    __half* Hs   = Ws + 128 * LDH;                            // H (k-major)   [128][LDH]

    const int tid  = threadIdx.x;
    const int row0 = blockIdx.x * BM;

    if (tid < 128) bias[tid] = Wb[tid];

    // ---- stage h, W, H: row r = tid>>2, each thread covers 32 cols ----
    {
        const int r = tid >> 2;
        const int q = tid & 3;
        int grow = row0 + r; if (grow >= N) grow = N - 1;
        const float4* hr = reinterpret_cast<const float4*>(h  + (size_t)grow * D);
        const float4* wr = reinterpret_cast<const float4*>(Ww + (size_t)r    * D);
        const float4* mr = reinterpret_cast<const float4*>(Hm + (size_t)r    * D);
        #pragma unroll
        for (int u = 0; u < 8; ++u) {
            const int c = q * 32 + u * 4;
            float4 v = hr[q * 8 + u];
            uint2 p;
            p.x = h2u(__floats2half2_rn(v.x, v.y));
            p.y = h2u(__floats2half2_rn(v.z, v.w));
            *reinterpret_cast<uint2*>(&As[r * LDH + c]) = p;
            v = wr[q * 8 + u];
            p.x = h2u(__floats2half2_rn(v.x, v.y));
            p.y = h2u(__floats2half2_rn(v.z, v.w));
            *reinterpret_cast<uint2*>(&Ws[r * LDH + c]) = p;
            v = mr[q * 8 + u];
            p.x = h2u(__floats2half2_rn(v.x, v.y));
            p.y = h2u(__floats2half2_rn(v.z, v.w));
            *reinterpret_cast<uint2*>(&Hs[r * LDH + c]) = p;
        }
    }
    __syncthreads();

    const int warp = tid >> 5;
    const int lane = tid & 31;
    const int m0   = (warp >> 2) * 32;       // warp row base (0,32,64,96)
    const int n0   = (warp & 3) * 32;        // warp col base (0,32,64,96)
    const int qr   = lane >> 2;
    const int qc   = (lane & 3) * 2;

    // per-lane ldmatrix address components (validated in R10/R12)
    const int aRow = (lane & 15);
    const int aCol = (lane >> 4) * 8;
    const int bRow = ((lane >> 4) << 3) + (lane & 7);    // n-major B (Ws)
    const int bCol = ((lane >> 3) & 1) * 8;
    const int tRow = ((lane >> 3) & 1) * 8 + (lane & 7); // trans B (Hs): k-row
    const int tCol = (lane >> 4) * 8;

    float acc[2][4][4];
    #pragma unroll
    for (int mt = 0; mt < 2; ++mt)
        #pragma unroll
        for (int nt = 0; nt < 4; ++nt)
            #pragma unroll
            for (int j = 0; j < 4; ++j) acc[mt][nt][j] = 0.f;

    // ================= GEMM1: hp = h @ W^T =================
    #pragma unroll
    for (int ks = 0; ks < 8; ++ks) {
        const int kb = ks * 16;
        uint32_t A[2][4], B[2][4];
        #pragma unroll
        for (int mt = 0; mt < 2; ++mt)
            ldm_x4(A[mt][0], A[mt][1], A[mt][2], A[mt][3],
                   &As[(m0 + mt * 16 + aRow) * LDH + kb + aCol]);
        #pragma unroll
        for (int np = 0; np < 2; ++np)
            ldm_x4(B[np][0], B[np][1], B[np][2], B[np][3],
                   &Ws[(n0 + np * 16 + bRow) * LDH + kb + bCol]);
        #pragma unroll
        for (int mt = 0; mt < 2; ++mt)
            #pragma unroll
            for (int nt = 0; nt < 4; ++nt)
                mma16816(acc[mt][nt],
                         A[mt][0], A[mt][1], A[mt][2], A[mt][3],
                         B[nt >> 1][(nt & 1) * 2], B[nt >> 1][(nt & 1) * 2 + 1]);
    }

    __syncthreads();   // all GEMM1 reads of As/Ws complete

    // ---- epilogue 1: +bias, f16, scatter into As (hp) ----
    #pragma unroll
    for (int mt = 0; mt < 2; ++mt) {
        const int r = m0 + mt * 16 + qr;
        #pragma unroll
        for (int nt = 0; nt < 4; ++nt) {
            const int c = n0 + nt * 8 + qc;
            const float b0f = bias[c], b1f = bias[c + 1];
            *reinterpret_cast<uint32_t*>(&As[r * LDH + c]) =
                h2u(__floats2half2_rn(acc[mt][nt][0] + b0f, acc[mt][nt][1] + b1f));
            *reinterpret_cast<uint32_t*>(&As[(r + 8) * LDH + c]) =
                h2u(__floats2half2_rn(acc[mt][nt][2] + b0f, acc[mt][nt][3] + b1f));
        }
    }
    __syncthreads();   // hp visible to all

    // ---- coalesced g_hp store from smem ----
    {
        const int r = tid >> 2;
        const int q = tid & 3;
        const int grow = row0 + r;
        if (grow < N) {
            const uint4* srcp = reinterpret_cast<const uint4*>(&As[r * LDH + q * 32]);
            uint4* dstp = reinterpret_cast<uint4*>(&g_hp[(size_t)grow * D + q * 32]);
            #pragma unroll
            for (int u = 0; u < 4; ++u) dstp[u] = srcp[u];
        }
    }

    // ================= GEMM2: hpH = hp @ H =================
    #pragma unroll
    for (int mt = 0; mt < 2; ++mt)
        #pragma unroll
        for (int nt = 0; nt < 4; ++nt)
            #pragma unroll
            for (int j = 0; j < 4; ++j) acc[mt][nt][j] = 0.f;

    #pragma unroll
    for (int ks = 0; ks < 8; ++ks) {
        const int kb = ks * 16;
        uint32_t A[2][4], B[2][4];
        #pragma unroll
        for (int mt = 0; mt < 2; ++mt)
            ldm_x4(A[mt][0], A[mt][1], A[mt][2], A[mt][3],
                   &As[(m0 + mt * 16 + aRow) * LDH + kb + aCol]);
        #pragma unroll
        for (int np = 0; np < 2; ++np)
            ldm_x4_t(B[np][0], B[np][1], B[np][2], B[np][3],
                     &Hs[(kb + tRow) * LDH + n0 + np * 16 + tCol]);
        #pragma unroll
        for (int mt = 0; mt < 2; ++mt)
            #pragma unroll
            for (int nt = 0; nt < 4; ++nt)
                mma16816(acc[mt][nt],
                         A[mt][0], A[mt][1], A[mt][2], A[mt][3],
                         B[nt >> 1][(nt & 1) * 2], B[nt >> 1][(nt & 1) * 2 + 1]);
    }

    // ---- epilogue 2: f16, scatter into Ws (no one reads Ws during GEMM2) ----
    #pragma unroll
    for (int mt = 0; mt < 2; ++mt) {
        const int r = m0 + mt * 16 + qr;
        #pragma unroll
        for (int nt = 0; nt < 4; ++nt) {
            const int c = n0 + nt * 8 + qc;
            *reinterpret_cast<uint32_t*>(&Ws[r * LDH + c]) =
                h2u(__floats2half2_rn(acc[mt][nt][0], acc[mt][nt][1]));
            *reinterpret_cast<uint32_t*>(&Ws[(r + 8) * LDH + c]) =
                h2u(__floats2half2_rn(acc[mt][nt][2], acc[mt][nt][3]));
        }
    }
    __syncthreads();

    // ---- coalesced g_hpH store ----
    {
        const int r = tid >> 2;
        const int q = tid & 3;
        const int grow = row0 + r;
        if (grow < N) {
            const uint4* srcp = reinterpret_cast<const uint4*>(&Ws[r * LDH + q * 32]);
            uint4* dstp = reinterpret_cast<uint4*>(&g_hpH[(size_t)grow * D + q * 32]);
            #pragma unroll
            for (int u = 0; u < 4; ++u) dstp[u] = srcp[u];
        }
    }
}

// ============================================================================
// Edge kernel: 2 edges per 16-lane group (4 independent LDG.128 per thread
// for MLP; edge kernel was latency-bound at issue=48%).
// ============================================================================
__global__ __launch_bounds__(256)
void edge_kernel(const int* __restrict__ src,
                 const int* __restrict__ dst,
                 float* __restrict__ out, int E, int N)
{
    int grp  = (int)((blockIdx.x * blockDim.x + threadIdx.x) >> 4);
    int slot = threadIdx.x & 15;
    int e0   = grp * 2;
    if (e0 >= E) return;
    int e1 = e0 + 1;
    bool has1 = (e1 < E);

    int s0 = __ldg(src + e0);
    int d0 = __ldg(dst + e0);
    int s1 = has1 ? __ldg(src + e1) : s0;
    int d1 = has1 ? __ldg(dst + e1) : d0;
    s0 = min(max(s0, 0), N - 1);  d0 = min(max(d0, 0), N - 1);
    s1 = min(max(s1, 0), N - 1);  d1 = min(max(d1, 0), N - 1);

    // 4 independent 16B gathers in flight
    uint4 a0 = reinterpret_cast<const uint4*>(g_hp  + (size_t)s0 * D)[slot];
    uint4 b0 = reinterpret_cast<const uint4*>(g_hpH + (size_t)d0 * D)[slot];
    uint4 a1 = reinterpret_cast<const uint4*>(g_hp  + (size_t)s1 * D)[slot];
    uint4 b1 = reinterpret_cast<const uint4*>(g_hpH + (size_t)d1 * D)[slot];

    float sum0 = 0.f, sum1 = 0.f;
    {
        const __half2* ah = reinterpret_cast<const __half2*>(&a0);
        const __half2* bh = reinterpret_cast<const __half2*>(&b0);
        #pragma unroll
        for (int i = 0; i < 4; ++i) {
            float2 fa = __half22float2(ah[i]);
            float2 fb = __half22float2(bh[i]);
            float dx = fa.x - fb.x, dy = fa.y - fb.y;
            sum0 = fmaf(dx, dx, sum0);
            sum0 = fmaf(dy, dy, sum0);
        }
    }
    {
        const __half2* ah = reinterpret_cast<const __half2*>(&a1);
        const __half2* bh = reinterpret_cast<const __half2*>(&b1);
        #pragma unroll
        for (int i = 0; i < 4; ++i) {
            float2 fa = __half22float2(ah[i]);
            float2 fb = __half22float2(bh[i]);
            float dx = fa.x - fb.x, dy = fa.y - fb.y;
            sum1 = fmaf(dx, dx, sum1);
            sum1 = fmaf(dy, dy, sum1);
        }
    }
    #pragma unroll
    for (int off = 8; off; off >>= 1) {
        sum0 += __shfl_xor_sync(0xffffffffu, sum0, off);
        sum1 += __shfl_xor_sync(0xffffffffu, sum1, off);
    }

    if (slot == 0) {
        out[e0] = sum0;
        if (has1) out[e1] = sum1;
    }
}

extern "C" void kernel_launch(void* const* d_in, const int* in_sizes, int n_in,
                              void* d_out, int out_size)
{
    const float* h   = (const float*)d_in[0];
    const int*   src = (const int*)d_in[1];
    const int*   dst = (const int*)d_in[2];
    const float* Ww  = (const float*)d_in[3];
    const float* Wb  = (const float*)d_in[4];
    const float* Hm  = (const float*)d_in[5];
    float*       out = (float*)d_out;

    int N = in_sizes[0] / D;
    if (N > NMAX) N = NMAX;
    int E = in_sizes[1];

    const int smem_bytes = 512 + 3 * 128 * LDH * (int)sizeof(__half); // 104960 B
    cudaFuncSetAttribute(node_kernel,
                         cudaFuncAttributeMaxDynamicSharedMemorySize, smem_bytes);

    int nblocks = (N + BM - 1) / BM;
    node_kernel<<<nblocks, 512, smem_bytes>>>(h, Ww, Wb, Hm, N);

    // 16 lanes per 2 edges -> 16 groups (32 edges) per 256-thread block
    int eblocks = ((E + 1) / 2 + 15) / 16;
    edge_kernel<<<eblocks, 256>>>(src, dst, out, E, N);
}

// round 16
// speedup vs baseline: 1.1478x; 1.0184x over previous
#include <cuda_runtime.h>
#include <cuda_fp16.h>
#include <cstdint>

#define D    128
#define BM   128
#define NMAX 100000
#define LDH  136   // padded row stride in halves (272B: conflict-free ldmatrix)

// fp16 node features for the edge gather (51MB working set fits L2).
__device__ __half g_hp [(size_t)NMAX * D];
__device__ __half g_hpH[(size_t)NMAX * D];

__device__ __forceinline__ uint32_t h2u(__half2 v) {
    return *reinterpret_cast<uint32_t*>(&v);
}
__device__ __forceinline__ __half2 u2h(uint32_t v) {
    return *reinterpret_cast<__half2*>(&v);
}

// f16-accumulate legacy mma: 2x pipe rate vs f32-accum on prior arches.
__device__ __forceinline__ void mma16816h(uint32_t& c0, uint32_t& c1,
                                          uint32_t a0, uint32_t a1,
                                          uint32_t a2, uint32_t a3,
                                          uint32_t b0, uint32_t b1) {
    asm volatile(
        "mma.sync.aligned.m16n8k16.row.col.f16.f16.f16.f16 "
        "{%0,%1}, {%2,%3,%4,%5}, {%6,%7}, {%0,%1};"
        : "+r"(c0), "+r"(c1)
        : "r"(a0), "r"(a1), "r"(a2), "r"(a3), "r"(b0), "r"(b1));
}
__device__ __forceinline__ void ldm_x4(uint32_t& r0, uint32_t& r1,
                                       uint32_t& r2, uint32_t& r3,
                                       const __half* p) {
    uint32_t a = (uint32_t)__cvta_generic_to_shared(p);
    asm volatile("ldmatrix.sync.aligned.m8n8.x4.shared.b16 {%0,%1,%2,%3}, [%4];"
                 : "=r"(r0), "=r"(r1), "=r"(r2), "=r"(r3) : "r"(a));
}
__device__ __forceinline__ void ldm_x4_t(uint32_t& r0, uint32_t& r1,
                                         uint32_t& r2, uint32_t& r3,
                                         const __half* p) {
    uint32_t a = (uint32_t)__cvta_generic_to_shared(p);
    asm volatile("ldmatrix.sync.aligned.m8n8.x4.trans.shared.b16 {%0,%1,%2,%3}, [%4];"
                 : "=r"(r0), "=r"(r1), "=r"(r2), "=r"(r3) : "r"(a));
}

// ============================================================================
// Node transform: hp = h@W^T + b ; hpH = hp@H.  fp16 HMMA, fp16 accumulate.
// 512 threads = 16 warps as 4(m) x 4(n); warp tile = 32 rows x 32 cols.
// ============================================================================
__global__ __launch_bounds__(512, 1)
void node_kernel(const float* __restrict__ h,
                 const float* __restrict__ Ww,
                 const float* __restrict__ Wb,
                 const float* __restrict__ Hm,
                 int N)
{
    extern __shared__ char smem[];
    __half2* biash = reinterpret_cast<__half2*>(smem);        // 64 half2 = 256 B
    __half*  As    = reinterpret_cast<__half*>(smem + 512);   // h tile -> hp   [128][LDH]
    __half*  Ws    = As + 128 * LDH;                          // W (n-major) -> hpH stage
    __half*  Hs    = Ws + 128 * LDH;                          // H (k-major)   [128][LDH]

    const int tid  = threadIdx.x;
    const int row0 = blockIdx.x * BM;

    if (tid < 64) {
        const float2 b2 = reinterpret_cast<const float2*>(Wb)[tid];
        biash[tid] = __floats2half2_rn(b2.x, b2.y);
    }

    // ---- stage h, W, H: row r = tid>>2, each thread covers 32 cols ----
    {
        const int r = tid >> 2;
        const int q = tid & 3;
        int grow = row0 + r; if (grow >= N) grow = N - 1;
        const float4* hr = reinterpret_cast<const float4*>(h  + (size_t)grow * D);
        const float4* wr = reinterpret_cast<const float4*>(Ww + (size_t)r    * D);
        const float4* mr = reinterpret_cast<const float4*>(Hm + (size_t)r    * D);
        #pragma unroll
        for (int u = 0; u < 8; ++u) {
            const int c = q * 32 + u * 4;
            float4 v = hr[q * 8 + u];
            uint2 p;
            p.x = h2u(__floats2half2_rn(v.x, v.y));
            p.y = h2u(__floats2half2_rn(v.z, v.w));
            *reinterpret_cast<uint2*>(&As[r * LDH + c]) = p;
            v = wr[q * 8 + u];
            p.x = h2u(__floats2half2_rn(v.x, v.y));
            p.y = h2u(__floats2half2_rn(v.z, v.w));
            *reinterpret_cast<uint2*>(&Ws[r * LDH + c]) = p;
            v = mr[q * 8 + u];
            p.x = h2u(__floats2half2_rn(v.x, v.y));
            p.y = h2u(__floats2half2_rn(v.z, v.w));
            *reinterpret_cast<uint2*>(&Hs[r * LDH + c]) = p;
        }
    }
    __syncthreads();

    const int warp = tid >> 5;
    const int lane = tid & 31;
    const int m0   = (warp >> 2) * 32;       // warp row base (0,32,64,96)
    const int n0   = (warp & 3) * 32;        // warp col base (0,32,64,96)
    const int qr   = lane >> 2;
    const int qc   = (lane & 3) * 2;

    // per-lane ldmatrix address components (validated in R10/R12/R15)
    const int aRow = (lane & 15);
    const int aCol = (lane >> 4) * 8;
    const int bRow = ((lane >> 4) << 3) + (lane & 7);    // n-major B (Ws)
    const int bCol = ((lane >> 3) & 1) * 8;
    const int tRow = ((lane >> 3) & 1) * 8 + (lane & 7); // trans B (Hs): k-row
    const int tCol = (lane >> 4) * 8;

    // f16 accumulators: [mt][nt][2] regs; c0 = rows qr, c1 = rows qr+8
    uint32_t acc[2][4][2];
    #pragma unroll
    for (int mt = 0; mt < 2; ++mt)
        #pragma unroll
        for (int nt = 0; nt < 4; ++nt)
            acc[mt][nt][0] = acc[mt][nt][1] = 0u;

    // ================= GEMM1: hp = h @ W^T =================
    #pragma unroll
    for (int ks = 0; ks < 8; ++ks) {
        const int kb = ks * 16;
        uint32_t A[2][4], B[2][4];
        #pragma unroll
        for (int mt = 0; mt < 2; ++mt)
            ldm_x4(A[mt][0], A[mt][1], A[mt][2], A[mt][3],
                   &As[(m0 + mt * 16 + aRow) * LDH + kb + aCol]);
        #pragma unroll
        for (int np = 0; np < 2; ++np)
            ldm_x4(B[np][0], B[np][1], B[np][2], B[np][3],
                   &Ws[(n0 + np * 16 + bRow) * LDH + kb + bCol]);
        #pragma unroll
        for (int mt = 0; mt < 2; ++mt)
            #pragma unroll
            for (int nt = 0; nt < 4; ++nt)
                mma16816h(acc[mt][nt][0], acc[mt][nt][1],
                          A[mt][0], A[mt][1], A[mt][2], A[mt][3],
                          B[nt >> 1][(nt & 1) * 2], B[nt >> 1][(nt & 1) * 2 + 1]);
    }

    __syncthreads();   // all GEMM1 reads of As/Ws complete

    // ---- epilogue 1: +bias (half2), scatter into As (hp) ----
    #pragma unroll
    for (int mt = 0; mt < 2; ++mt) {
        const int r = m0 + mt * 16 + qr;
        #pragma unroll
        for (int nt = 0; nt < 4; ++nt) {
            const int c = n0 + nt * 8 + qc;
            const __half2 b2 = biash[c >> 1];
            *reinterpret_cast<uint32_t*>(&As[r * LDH + c]) =
                h2u(__hadd2(u2h(acc[mt][nt][0]), b2));
            *reinterpret_cast<uint32_t*>(&As[(r + 8) * LDH + c]) =
                h2u(__hadd2(u2h(acc[mt][nt][1]), b2));
        }
    }
    __syncthreads();   // hp visible to all

    // ---- coalesced g_hp store from smem ----
    {
        const int r = tid >> 2;
        const int q = tid & 3;
        const int grow = row0 + r;
        if (grow < N) {
            const uint4* srcp = reinterpret_cast<const uint4*>(&As[r * LDH + q * 32]);
            uint4* dstp = reinterpret_cast<uint4*>(&g_hp[(size_t)grow * D + q * 32]);
            #pragma unroll
            for (int u = 0; u < 4; ++u) dstp[u] = srcp[u];
        }
    }

    // ================= GEMM2: hpH = hp @ H =================
    #pragma unroll
    for (int mt = 0; mt < 2; ++mt)
        #pragma unroll
        for (int nt = 0; nt < 4; ++nt)
            acc[mt][nt][0] = acc[mt][nt][1] = 0u;

    #pragma unroll
    for (int ks = 0; ks < 8; ++ks) {
        const int kb = ks * 16;
        uint32_t A[2][4], B[2][4];
        #pragma unroll
        for (int mt = 0; mt < 2; ++mt)
            ldm_x4(A[mt][0], A[mt][1], A[mt][2], A[mt][3],
                   &As[(m0 + mt * 16 + aRow) * LDH + kb + aCol]);
        #pragma unroll
        for (int np = 0; np < 2; ++np)
            ldm_x4_t(B[np][0], B[np][1], B[np][2], B[np][3],
                     &Hs[(kb + tRow) * LDH + n0 + np * 16 + tCol]);
        #pragma unroll
        for (int mt = 0; mt < 2; ++mt)
            #pragma unroll
            for (int nt = 0; nt < 4; ++nt)
                mma16816h(acc[mt][nt][0], acc[mt][nt][1],
                          A[mt][0], A[mt][1], A[mt][2], A[mt][3],
                          B[nt >> 1][(nt & 1) * 2], B[nt >> 1][(nt & 1) * 2 + 1]);
    }

    // ---- epilogue 2: scatter into Ws (no one reads Ws during GEMM2) ----
    #pragma unroll
    for (int mt = 0; mt < 2; ++mt) {
        const int r = m0 + mt * 16 + qr;
        #pragma unroll
        for (int nt = 0; nt < 4; ++nt) {
            const int c = n0 + nt * 8 + qc;
            *reinterpret_cast<uint32_t*>(&Ws[r * LDH + c])       = acc[mt][nt][0];
            *reinterpret_cast<uint32_t*>(&Ws[(r + 8) * LDH + c]) = acc[mt][nt][1];
        }
    }
    __syncthreads();

    // ---- coalesced g_hpH store ----
    {
        const int r = tid >> 2;
        const int q = tid & 3;
        const int grow = row0 + r;
        if (grow < N) {
            const uint4* srcp = reinterpret_cast<const uint4*>(&Ws[r * LDH + q * 32]);
            uint4* dstp = reinterpret_cast<uint4*>(&g_hpH[(size_t)grow * D + q * 32]);
            #pragma unroll
            for (int u = 0; u < 4; ++u) dstp[u] = srcp[u];
        }
    }
}

// ============================================================================
// Edge kernel: 2 edges per 16-lane group, 4 independent LDG.128 per thread.
// (unchanged from R15)
// ============================================================================
__global__ __launch_bounds__(256)
void edge_kernel(const int* __restrict__ src,
                 const int* __restrict__ dst,
                 float* __restrict__ out, int E, int N)
{
    int grp  = (int)((blockIdx.x * blockDim.x + threadIdx.x) >> 4);
    int slot = threadIdx.x & 15;
    int e0   = grp * 2;
    if (e0 >= E) return;
    int e1 = e0 + 1;
    bool has1 = (e1 < E);

    int s0 = __ldg(src + e0);
    int d0 = __ldg(dst + e0);
    int s1 = has1 ? __ldg(src + e1) : s0;
    int d1 = has1 ? __ldg(dst + e1) : d0;
    s0 = min(max(s0, 0), N - 1);  d0 = min(max(d0, 0), N - 1);
    s1 = min(max(s1, 0), N - 1);  d1 = min(max(d1, 0), N - 1);

    uint4 a0 = reinterpret_cast<const uint4*>(g_hp  + (size_t)s0 * D)[slot];
    uint4 b0 = reinterpret_cast<const uint4*>(g_hpH + (size_t)d0 * D)[slot];
    uint4 a1 = reinterpret_cast<const uint4*>(g_hp  + (size_t)s1 * D)[slot];
    uint4 b1 = reinterpret_cast<const uint4*>(g_hpH + (size_t)d1 * D)[slot];

    float sum0 = 0.f, sum1 = 0.f;
    {
        const __half2* ah = reinterpret_cast<const __half2*>(&a0);
        const __half2* bh = reinterpret_cast<const __half2*>(&b0);
        #pragma unroll
        for (int i = 0; i < 4; ++i) {
            float2 fa = __half22float2(ah[i]);
            float2 fb = __half22float2(bh[i]);
            float dx = fa.x - fb.x, dy = fa.y - fb.y;
            sum0 = fmaf(dx, dx, sum0);
            sum0 = fmaf(dy, dy, sum0);
        }
    }
    {
        const __half2* ah = reinterpret_cast<const __half2*>(&a1);
        const __half2* bh = reinterpret_cast<const __half2*>(&b1);
        #pragma unroll
        for (int i = 0; i < 4; ++i) {
            float2 fa = __half22float2(ah[i]);
            float2 fb = __half22float2(bh[i]);
            float dx = fa.x - fb.x, dy = fa.y - fb.y;
            sum1 = fmaf(dx, dx, sum1);
            sum1 = fmaf(dy, dy, sum1);
        }
    }
    #pragma unroll
    for (int off = 8; off; off >>= 1) {
        sum0 += __shfl_xor_sync(0xffffffffu, sum0, off);
        sum1 += __shfl_xor_sync(0xffffffffu, sum1, off);
    }

    if (slot == 0) {
        out[e0] = sum0;
        if (has1) out[e1] = sum1;
    }
}

extern "C" void kernel_launch(void* const* d_in, const int* in_sizes, int n_in,
                              void* d_out, int out_size)
{
    const float* h   = (const float*)d_in[0];
    const int*   src = (const int*)d_in[1];
    const int*   dst = (const int*)d_in[2];
    const float* Ww  = (const float*)d_in[3];
    const float* Wb  = (const float*)d_in[4];
    const float* Hm  = (const float*)d_in[5];
    float*       out = (float*)d_out;

    int N = in_sizes[0] / D;
    if (N > NMAX) N = NMAX;
    int E = in_sizes[1];

    const int smem_bytes = 512 + 3 * 128 * LDH * (int)sizeof(__half); // 104960 B
    cudaFuncSetAttribute(node_kernel,
                         cudaFuncAttributeMaxDynamicSharedMemorySize, smem_bytes);

    int nblocks = (N + BM - 1) / BM;
    node_kernel<<<nblocks, 512, smem_bytes>>>(h, Ww, Wb, Hm, N);

    int eblocks = ((E + 1) / 2 + 15) / 16;
    edge_kernel<<<eblocks, 256>>>(src, dst, out, E, N);
}